// round 4
// baseline (speedup 1.0000x reference)
#include <cuda_runtime.h>
#include <cuda_bf16.h>
#include <cstdint>
#include <cstddef>

// ============================================================
// Problem constants
// ============================================================
#define NN   100000      // nodes
#define NE   1600000     // edges
#define NP   100096      // padded: 64*1564 = 128*782
#define NB64 1564        // GEMM row tiles (64 rows each)
#define D    256
#define DH   128

// ============================================================
// Device global scratch (no cudaMalloc allowed)
// ============================================================
__device__ __align__(256) __nv_bfloat16 g_xhi[(size_t)NP * D];
__device__ __align__(256) __nv_bfloat16 g_xlo[(size_t)NP * D];
__device__ __align__(256) float g_a[(size_t)NP * DH];   // relu(x@W2^T + b2)
__device__ __align__(256) float g_y[(size_t)NP * DH];   // x@W3^T (pre-aggregation)
__device__ __align__(256) __nv_bfloat16 g_w1hi[D * D],  g_w1lo[D * D];
__device__ __align__(256) __nv_bfloat16 g_w2hi[DH * D], g_w2lo[DH * D];
__device__ __align__(256) __nv_bfloat16 g_w3hi[DH * D], g_w3lo[DH * D];
__device__ __align__(256) __nv_bfloat16 g_wd1hi[D * D], g_wd1lo[D * D];
__device__ __align__(256) int g_rowptr[NN + 1];
__device__ __align__(256) int g_cursor[NN];
__device__ __align__(256) int g_cnt[NN];
__device__ __align__(256) int g_colidx[NE];
__device__ __align__(256) int g_src[NE];
__device__ __align__(256) int g_dst[NE];
__device__ int g_is64;

// ============================================================
// Helpers
// ============================================================
__device__ __forceinline__ uint32_t smem_u32(const void* p) {
    uint32_t a;
    asm("{ .reg .u64 t; cvta.to.shared.u64 t, %1; cvt.u32.u64 %0, t; }"
        : "=r"(a) : "l"(p));
    return a;
}

#define SW128(o) ((o) ^ (((o) >> 3) & 0x70))

__device__ __forceinline__ void cp16(uint32_t dst, const void* src) {
    asm volatile("cp.async.cg.shared.global [%0], [%1], 16;" :: "r"(dst), "l"(src));
}
__device__ __forceinline__ void cp_commit() {
    asm volatile("cp.async.commit_group;" ::: "memory");
}
template <int N>
__device__ __forceinline__ void cp_wait() {
    asm volatile("cp.async.wait_group %0;" :: "n"(N) : "memory");
}

__device__ __forceinline__ void ldsm4(uint32_t* r, uint32_t addr) {
    asm volatile("ldmatrix.sync.aligned.m8n8.x4.shared.b16 {%0,%1,%2,%3}, [%4];"
        : "=r"(r[0]), "=r"(r[1]), "=r"(r[2]), "=r"(r[3]) : "r"(addr));
}

__device__ __forceinline__ void mma16816(float* c, const uint32_t* a,
                                         uint32_t b0, uint32_t b1) {
    asm volatile(
        "mma.sync.aligned.m16n8k16.row.col.f32.bf16.bf16.f32 "
        "{%0,%1,%2,%3}, {%4,%5,%6,%7}, {%8,%9}, {%0,%1,%2,%3};"
        : "+f"(c[0]), "+f"(c[1]), "+f"(c[2]), "+f"(c[3])
        : "r"(a[0]), "r"(a[1]), "r"(a[2]), "r"(a[3]), "r"(b0), "r"(b1));
}

__device__ __forceinline__ void split_bf(float v, __nv_bfloat16& h, __nv_bfloat16& l) {
    h = __float2bfloat16(v);
    l = __float2bfloat16(v - __bfloat162float(h));
}
__device__ __forceinline__ uint32_t pack2(__nv_bfloat16 a, __nv_bfloat16 b) {
    __nv_bfloat162 t; t.x = a; t.y = b;
    return *reinterpret_cast<uint32_t*>(&t);
}

// ============================================================
// fp32 -> bf16 hi/lo split conversions
// ============================================================
__global__ void conv_x_kernel(const float* __restrict__ x) {
    size_t i4 = (size_t)blockIdx.x * blockDim.x + threadIdx.x;
    if (i4 >= (size_t)NP * 64) return;
    float4 v = make_float4(0.f, 0.f, 0.f, 0.f);
    if (i4 < (size_t)NN * 64) v = __ldg(((const float4*)x) + i4);
    __nv_bfloat16 h0, l0, h1, l1, h2, l2, h3, l3;
    split_bf(v.x, h0, l0); split_bf(v.y, h1, l1);
    split_bf(v.z, h2, l2); split_bf(v.w, h3, l3);
    ((uint2*)g_xhi)[i4] = make_uint2(pack2(h0, h1), pack2(h2, h3));
    ((uint2*)g_xlo)[i4] = make_uint2(pack2(l0, l1), pack2(l2, l3));
}

__global__ void conv_w_kernel(const float* __restrict__ w,
                              __nv_bfloat16* __restrict__ hi,
                              __nv_bfloat16* __restrict__ lo, int n4) {
    int i4 = blockIdx.x * blockDim.x + threadIdx.x;
    if (i4 >= n4) return;
    float4 v = __ldg(((const float4*)w) + i4);
    __nv_bfloat16 h0, l0, h1, l1, h2, l2, h3, l3;
    split_bf(v.x, h0, l0); split_bf(v.y, h1, l1);
    split_bf(v.z, h2, l2); split_bf(v.w, h3, l3);
    ((uint2*)hi)[i4] = make_uint2(pack2(h0, h1), pack2(h2, h3));
    ((uint2*)lo)[i4] = make_uint2(pack2(l0, l1), pack2(l2, l3));
}

// ============================================================
// edge_index dtype detection + extraction (int32 vs int64)
// ============================================================
__global__ void detect_kernel(const int* __restrict__ ei) {
    // If stored as int64 (little-endian, values in [0, 1e5)), every odd
    // int32 word is 0. For genuine int32 data, P(first 64 src values all
    // zero) is negligible.
    int z = 1;
    for (int i = 0; i < 64; i++)
        if (ei[2 * i + 1] != 0) { z = 0; break; }
    g_is64 = z;
}

__global__ void extract_kernel(const int* __restrict__ ei) {
    int e = blockIdx.x * blockDim.x + threadIdx.x;
    if (e >= NE) return;
    if (g_is64) {
        g_src[e] = __ldg(&ei[2 * e]);
        g_dst[e] = __ldg(&ei[2 * ((size_t)NE + e)]);
    } else {
        g_src[e] = __ldg(&ei[e]);
        g_dst[e] = __ldg(&ei[NE + e]);
    }
}

// ============================================================
// CSR build (by dst)
// ============================================================
__global__ void zero_cnt_kernel() {
    int i = blockIdx.x * blockDim.x + threadIdx.x;
    if (i < NN) g_cnt[i] = 0;
}

__global__ void count_edges_kernel() {
    int e = blockIdx.x * blockDim.x + threadIdx.x;
    if (e >= NE) return;
    unsigned d = (unsigned)g_dst[e];
    if (d < NN) atomicAdd(&g_cnt[d], 1);
}

__global__ void scan_kernel() {
    __shared__ int sd[1024];
    int t = threadIdx.x;
    const int PER = (NN + 1023) / 1024;   // 98
    int b = t * PER;
    int e = b + PER; if (e > NN) e = NN; if (b > NN) b = NN;
    int s = 0;
    for (int i = b; i < e; i++) s += g_cnt[i];
    sd[t] = s;
    __syncthreads();
    for (int off = 1; off < 1024; off <<= 1) {
        int v = (t >= off) ? sd[t - off] : 0;
        __syncthreads();
        sd[t] += v;
        __syncthreads();
    }
    int run = sd[t] - s;   // exclusive prefix
    for (int i = b; i < e; i++) {
        g_rowptr[i] = run;
        g_cursor[i] = run;
        run += g_cnt[i];
    }
    if (t == 1023) g_rowptr[NN] = run;
}

__global__ void fill_edges_kernel() {
    int e = blockIdx.x * blockDim.x + threadIdx.x;
    if (e >= NE) return;
    unsigned s = (unsigned)g_src[e];
    unsigned d = (unsigned)g_dst[e];
    if (s < NN && d < NN) {
        int p = atomicAdd(&g_cursor[d], 1);
        g_colidx[p] = (int)s;
    }
}

// ============================================================
// GEMM via warp-level mma.sync m16n8k16 bf16, hi/lo split (3 passes)
// CTA tile: 64 rows x 256 cols. 8 warps: 2 row-warps x 4 col-warps,
// warp tile 32x64. K chunked at 64, 2-stage cp.async pipeline.
//  MODE 0: layer-1   -> relu(+b1), l2norm, write g_xhi/g_xlo
//  MODE 1: mid layer -> cols[0:128)=relu(+b2)->g_a ; cols[128:256)=raw->g_y
//  MODE 2: final     -> h=relu(+bd1); out[row] = h . wd2 + bd2
// ============================================================
static constexpr int OF_AH = 0;                 //  8 KB (64 x 128B)
static constexpr int OF_AL = 8192;              //  8 KB
static constexpr int OF_BH = 16384;             // 32 KB (256 x 128B)
static constexpr int OF_BL = 49152;             // 32 KB
static constexpr int STG   = 81920;             // per-stage bytes
static constexpr int SMEM_SZ = 2 * STG;         // 160 KB
static constexpr int SSTRIDE = 260;             // staging row stride (floats)

template <int MODE>
__device__ __forceinline__ void issue_chunk(
        uint32_t sbuf, int rowbase, int kb,
        const __nv_bfloat16* BloH, const __nv_bfloat16* BloL,
        const __nv_bfloat16* BupH, const __nv_bfloat16* BupL, int tid) {
    // A: 64 rows x 4 uint4-groups per precision (Kc=64 -> 128B/row)
    for (int t = tid; t < 512; t += 256) {
        int r = t >> 3, g = t & 7;
        uint32_t so = SW128((uint32_t)(r * 128 + g * 16));
        size_t src = (size_t)(rowbase + r) * D + kb + g * 8;
        cp16(sbuf + OF_AH + so, g_xhi + src);
        cp16(sbuf + OF_AL + so, g_xlo + src);
    }
    // B: 256 rows x 8 groups per precision
    for (int t = tid; t < 2048; t += 256) {
        int r = t >> 3, g = t & 7;
        uint32_t so = SW128((uint32_t)(r * 128 + g * 16));
        const __nv_bfloat16 *sh, *sl;
        if (r < 128) {
            sh = BloH + (size_t)r * D + kb + g * 8;
            sl = BloL + (size_t)r * D + kb + g * 8;
        } else {
            sh = BupH + (size_t)(r - 128) * D + kb + g * 8;
            sl = BupL + (size_t)(r - 128) * D + kb + g * 8;
        }
        cp16(sbuf + OF_BH + so, sh);
        cp16(sbuf + OF_BL + so, sl);
    }
}

template <int MODE>
__global__ void __launch_bounds__(256, 1)
gemm_kernel(const float* __restrict__ bias, const float* __restrict__ wd2,
            const float* __restrict__ bd2, float* __restrict__ out) {
    extern __shared__ char smem[];
    uint32_t sb = smem_u32(smem);
    int tid = threadIdx.x, wid = tid >> 5, lane = tid & 31;
    int rowbase = blockIdx.x * 64;
    int wrow = wid & 1;        // 0..1  -> rows wrow*32
    int wcol = wid >> 1;       // 0..3  -> cols wcol*64

    const __nv_bfloat16 *BloH, *BloL, *BupH, *BupL;
    if (MODE == 0)      { BloH = g_w1hi;  BloL = g_w1lo;  BupH = g_w1hi + 128 * D;  BupL = g_w1lo + 128 * D; }
    else if (MODE == 1) { BloH = g_w2hi;  BloL = g_w2lo;  BupH = g_w3hi;            BupL = g_w3lo; }
    else                { BloH = g_wd1hi; BloL = g_wd1lo; BupH = g_wd1hi + 128 * D; BupL = g_wd1lo + 128 * D; }

    float c[2][8][4];
    #pragma unroll
    for (int mt = 0; mt < 2; mt++)
        #pragma unroll
        for (int nt = 0; nt < 8; nt++)
            #pragma unroll
            for (int q = 0; q < 4; q++) c[mt][nt][q] = 0.f;

    int q8 = lane >> 3, l8 = lane & 7;

    issue_chunk<MODE>(sb, rowbase, 0, BloH, BloL, BupH, BupL, tid);
    cp_commit();

    for (int ch = 0; ch < 4; ch++) {
        uint32_t buf = sb + (uint32_t)(ch & 1) * STG;
        if (ch < 3) {
            issue_chunk<MODE>(sb + (uint32_t)((ch + 1) & 1) * STG, rowbase,
                              (ch + 1) * 64, BloH, BloL, BupH, BupL, tid);
            cp_commit();
            cp_wait<1>();
        } else {
            cp_wait<0>();
        }
        __syncthreads();

        #pragma unroll
        for (int ks = 0; ks < 4; ks++) {
            uint32_t ah[2][4], al[2][4];
            #pragma unroll
            for (int mt = 0; mt < 2; mt++) {
                int row = wrow * 32 + mt * 16 + (q8 & 1) * 8 + l8;
                uint32_t off = SW128((uint32_t)(row * 128 + ks * 32 + (q8 >> 1) * 16));
                ldsm4(ah[mt], buf + OF_AH + off);
                ldsm4(al[mt], buf + OF_AL + off);
            }
            uint32_t bh[4][4], bl[4][4];
            #pragma unroll
            for (int nt = 0; nt < 4; nt++) {
                int nrow = wcol * 64 + nt * 16 + ((q8 >> 1) & 1) * 8 + l8;
                uint32_t off = SW128((uint32_t)(nrow * 128 + ks * 32 + (q8 & 1) * 16));
                ldsm4(bh[nt], buf + OF_BH + off);
                ldsm4(bl[nt], buf + OF_BL + off);
            }
            #pragma unroll
            for (int mt = 0; mt < 2; mt++)
                #pragma unroll
                for (int nt = 0; nt < 4; nt++) {
                    // lower n8 tile (regs 0,1) and upper n8 tile (regs 2,3)
                    mma16816(c[mt][nt * 2],     ah[mt], bh[nt][0], bh[nt][1]);
                    mma16816(c[mt][nt * 2],     ah[mt], bl[nt][0], bl[nt][1]);
                    mma16816(c[mt][nt * 2],     al[mt], bh[nt][0], bh[nt][1]);
                    mma16816(c[mt][nt * 2 + 1], ah[mt], bh[nt][2], bh[nt][3]);
                    mma16816(c[mt][nt * 2 + 1], ah[mt], bl[nt][2], bl[nt][3]);
                    mma16816(c[mt][nt * 2 + 1], al[mt], bh[nt][2], bh[nt][3]);
                }
        }
        __syncthreads();
    }

    // ---- stage accumulators into smem (overlays buf0; last compute used buf1)
    float* stage = reinterpret_cast<float*>(smem);
    #pragma unroll
    for (int mt = 0; mt < 2; mt++)
        #pragma unroll
        for (int nt = 0; nt < 8; nt++) {
            int r0  = wrow * 32 + mt * 16 + (lane >> 2);
            int col = wcol * 64 + nt * 8 + 2 * (lane & 3);
            float* p = stage + r0 * SSTRIDE + col;
            p[0] = c[mt][nt][0];
            p[1] = c[mt][nt][1];
            p[8 * SSTRIDE]     = c[mt][nt][2];
            p[8 * SSTRIDE + 1] = c[mt][nt][3];
        }
    __syncthreads();

    // ---- row-wise fused epilogue: warp per row, lane owns 8 contiguous cols
    for (int r = wid; r < 64; r += 8) {
        int gr = rowbase + r;
        bool ok = gr < NN;
        const float* rowp = stage + r * SSTRIDE + lane * 8;
        int cb = lane * 8;

        if (MODE == 0) {
            float v[8];
            float ss = 0.f;
            #pragma unroll
            for (int j = 0; j < 8; j++) {
                v[j] = fmaxf(rowp[j] + __ldg(&bias[cb + j]), 0.f);
                ss += v[j] * v[j];
            }
            #pragma unroll
            for (int off = 16; off >= 1; off >>= 1)
                ss += __shfl_xor_sync(0xffffffffu, ss, off);
            float rn = rsqrtf(ss);
            if (ok) {
                __nv_bfloat16 h[8], l[8];
                #pragma unroll
                for (int j = 0; j < 8; j++) split_bf(v[j] * rn, h[j], l[j]);
                *reinterpret_cast<uint4*>(g_xhi + (size_t)gr * D + cb) =
                    make_uint4(pack2(h[0], h[1]), pack2(h[2], h[3]),
                               pack2(h[4], h[5]), pack2(h[6], h[7]));
                *reinterpret_cast<uint4*>(g_xlo + (size_t)gr * D + cb) =
                    make_uint4(pack2(l[0], l[1]), pack2(l[2], l[3]),
                               pack2(l[4], l[5]), pack2(l[6], l[7]));
            }
        } else if (MODE == 1) {
            float v[8];
            if (lane < 16) {
                #pragma unroll
                for (int j = 0; j < 8; j++)
                    v[j] = fmaxf(rowp[j] + __ldg(&bias[cb + j]), 0.f);
                if (ok) {
                    float4* dst = reinterpret_cast<float4*>(g_a + (size_t)gr * DH + cb);
                    dst[0] = make_float4(v[0], v[1], v[2], v[3]);
                    dst[1] = make_float4(v[4], v[5], v[6], v[7]);
                }
            } else {
                #pragma unroll
                for (int j = 0; j < 8; j++) v[j] = rowp[j];
                if (ok) {
                    float4* dst = reinterpret_cast<float4*>(g_y + (size_t)gr * DH + (cb - 128));
                    dst[0] = make_float4(v[0], v[1], v[2], v[3]);
                    dst[1] = make_float4(v[4], v[5], v[6], v[7]);
                }
            }
        } else {
            float acc = 0.f;
            #pragma unroll
            for (int j = 0; j < 8; j++) {
                float vv = fmaxf(rowp[j] + __ldg(&bias[cb + j]), 0.f);
                acc += vv * __ldg(&wd2[cb + j]);
            }
            #pragma unroll
            for (int off = 16; off >= 1; off >>= 1)
                acc += __shfl_xor_sync(0xffffffffu, acc, off);
            if (lane == 0 && ok) out[gr] = acc + __ldg(bd2);
        }
    }
}

// ============================================================
// Fused CSR gather-reduce + bias + relu + l2norm + bf16-split store
// One warp per dst node; lane owns 4 cols of each 128-wide half.
// ============================================================
__global__ void agg_combine_kernel(const float* __restrict__ b3) {
    int gw = (blockIdx.x * blockDim.x + threadIdx.x) >> 5;
    int lane = threadIdx.x & 31;
    if (gw >= NN) return;
    int n = gw;
    int beg = __ldg(&g_rowptr[n]);
    int end = __ldg(&g_rowptr[n + 1]);

    float ax = 0.f, ay = 0.f, az = 0.f, aw = 0.f;
    for (int i = beg; i < end; i++) {
        int s = __ldg(&g_colidx[i]);
        float4 v = __ldg(reinterpret_cast<const float4*>(g_y + (size_t)s * DH) + lane);
        ax += v.x; ay += v.y; az += v.z; aw += v.w;
    }
    float4 av = *(reinterpret_cast<const float4*>(g_a + (size_t)n * DH) + lane);
    float4 bb = __ldg(reinterpret_cast<const float4*>(b3) + lane);
    float m0 = fmaxf(ax + bb.x, 0.f);
    float m1 = fmaxf(ay + bb.y, 0.f);
    float m2 = fmaxf(az + bb.z, 0.f);
    float m3 = fmaxf(aw + bb.w, 0.f);

    float ss = av.x * av.x + av.y * av.y + av.z * av.z + av.w * av.w
             + m0 * m0 + m1 * m1 + m2 * m2 + m3 * m3;
    #pragma unroll
    for (int off = 16; off >= 1; off >>= 1)
        ss += __shfl_xor_sync(0xffffffffu, ss, off);
    float rn = rsqrtf(ss);

    size_t base = (size_t)n * D;
    {
        __nv_bfloat16 h0, l0, h1, l1, h2, l2, h3, l3;
        split_bf(av.x * rn, h0, l0); split_bf(av.y * rn, h1, l1);
        split_bf(av.z * rn, h2, l2); split_bf(av.w * rn, h3, l3);
        *reinterpret_cast<uint2*>(g_xhi + base + lane * 4) = make_uint2(pack2(h0, h1), pack2(h2, h3));
        *reinterpret_cast<uint2*>(g_xlo + base + lane * 4) = make_uint2(pack2(l0, l1), pack2(l2, l3));
    }
    {
        __nv_bfloat16 h0, l0, h1, l1, h2, l2, h3, l3;
        split_bf(m0 * rn, h0, l0); split_bf(m1 * rn, h1, l1);
        split_bf(m2 * rn, h2, l2); split_bf(m3 * rn, h3, l3);
        *reinterpret_cast<uint2*>(g_xhi + base + 128 + lane * 4) = make_uint2(pack2(h0, h1), pack2(h2, h3));
        *reinterpret_cast<uint2*>(g_xlo + base + 128 + lane * 4) = make_uint2(pack2(l0, l1), pack2(l2, l3));
    }
}

// ============================================================
// Host launcher
// ============================================================
extern "C" void kernel_launch(void* const* d_in, const int* in_sizes, int n_in,
                              void* d_out, int out_size) {
    const float* x   = (const float*)d_in[0];
    const int*   ei  = (const int*)d_in[1];    // int32 or int64 (auto-detected)
    const float* W1  = (const float*)d_in[2];
    const float* b1  = (const float*)d_in[3];
    const float* W2  = (const float*)d_in[4];
    const float* b2  = (const float*)d_in[5];
    const float* W3  = (const float*)d_in[6];
    const float* b3  = (const float*)d_in[7];
    const float* Wd1 = (const float*)d_in[8];
    const float* bd1 = (const float*)d_in[9];
    const float* Wd2 = (const float*)d_in[10];
    const float* bd2 = (const float*)d_in[11];
    float* out = (float*)d_out;

    cudaFuncSetAttribute(gemm_kernel<0>, cudaFuncAttributeMaxDynamicSharedMemorySize, SMEM_SZ);
    cudaFuncSetAttribute(gemm_kernel<1>, cudaFuncAttributeMaxDynamicSharedMemorySize, SMEM_SZ);
    cudaFuncSetAttribute(gemm_kernel<2>, cudaFuncAttributeMaxDynamicSharedMemorySize, SMEM_SZ);

    void *pw1h, *pw1l, *pw2h, *pw2l, *pw3h, *pw3l, *pd1h, *pd1l;
    cudaGetSymbolAddress(&pw1h, g_w1hi);  cudaGetSymbolAddress(&pw1l, g_w1lo);
    cudaGetSymbolAddress(&pw2h, g_w2hi);  cudaGetSymbolAddress(&pw2l, g_w2lo);
    cudaGetSymbolAddress(&pw3h, g_w3hi);  cudaGetSymbolAddress(&pw3l, g_w3lo);
    cudaGetSymbolAddress(&pd1h, g_wd1hi); cudaGetSymbolAddress(&pd1l, g_wd1lo);

    // input conversions (fp32 -> bf16 hi/lo)
    conv_x_kernel<<<(int)(((size_t)NP * 64 + 255) / 256), 256>>>(x);
    conv_w_kernel<<<64, 256>>>(W1,  (__nv_bfloat16*)pw1h, (__nv_bfloat16*)pw1l, D * D / 4);
    conv_w_kernel<<<32, 256>>>(W2,  (__nv_bfloat16*)pw2h, (__nv_bfloat16*)pw2l, DH * D / 4);
    conv_w_kernel<<<32, 256>>>(W3,  (__nv_bfloat16*)pw3h, (__nv_bfloat16*)pw3l, DH * D / 4);
    conv_w_kernel<<<64, 256>>>(Wd1, (__nv_bfloat16*)pd1h, (__nv_bfloat16*)pd1l, D * D / 4);

    // edge extraction + CSR build (by dst)
    detect_kernel<<<1, 1>>>(ei);
    extract_kernel<<<(NE + 255) / 256, 256>>>(ei);
    zero_cnt_kernel<<<(NN + 255) / 256, 256>>>();
    count_edges_kernel<<<(NE + 255) / 256, 256>>>();
    scan_kernel<<<1, 1024>>>();
    fill_edges_kernel<<<(NE + 255) / 256, 256>>>();

    // layer 1: x = l2norm(relu(x @ W1^T + b1))
    gemm_kernel<0><<<NB64, 256, SMEM_SZ>>>(b1, nullptr, nullptr, nullptr);

    // 2 conv layers
    for (int l = 0; l < 2; l++) {
        gemm_kernel<1><<<NB64, 256, SMEM_SZ>>>(b2, nullptr, nullptr, nullptr);
        agg_combine_kernel<<<(NN * 32 + 255) / 256, 256>>>(b3);
    }

    // head: out = relu(x @ Wd1^T + bd1) @ Wd2^T + bd2
    gemm_kernel<2><<<NB64, 256, SMEM_SZ>>>(bd1, Wd2, bd2, out);
}

// round 5
// speedup vs baseline: 1.0286x; 1.0286x over previous
#include <cuda_runtime.h>
#include <cuda_bf16.h>
#include <cstdint>
#include <cstddef>

// ============================================================
// Problem constants
// ============================================================
#define NN   100000      // nodes
#define NE   1600000     // edges
#define NP   100096      // padded: 128*782
#define NB128 782        // GEMM row tiles (128 rows each)
#define D    256
#define DH   128

// ============================================================
// Device global scratch (no cudaMalloc allowed)
// ============================================================
__device__ __align__(256) __nv_bfloat16 g_xhi[(size_t)NP * D];
__device__ __align__(256) __nv_bfloat16 g_xlo[(size_t)NP * D];
__device__ __align__(256) float g_a[(size_t)NP * DH];   // relu(x@W2^T + b2)
__device__ __align__(256) float g_y[(size_t)NP * DH];   // x@W3^T (pre-aggregation)
__device__ __align__(256) __nv_bfloat16 g_w1hi[D * D],  g_w1lo[D * D];
__device__ __align__(256) __nv_bfloat16 g_w2hi[DH * D], g_w2lo[DH * D];
__device__ __align__(256) __nv_bfloat16 g_w3hi[DH * D], g_w3lo[DH * D];
__device__ __align__(256) __nv_bfloat16 g_wd1hi[D * D], g_wd1lo[D * D];
__device__ __align__(256) int g_rowptr[NN + 1];
__device__ __align__(256) int g_cursor[NN];
__device__ __align__(256) int g_cnt[NN];
__device__ __align__(256) int g_colidx[NE];
__device__ __align__(256) int g_src[NE];
__device__ __align__(256) int g_dst[NE];
__device__ int g_is64;

// ============================================================
// Helpers
// ============================================================
__device__ __forceinline__ uint32_t smem_u32(const void* p) {
    uint32_t a;
    asm("{ .reg .u64 t; cvta.to.shared.u64 t, %1; cvt.u32.u64 %0, t; }"
        : "=r"(a) : "l"(p));
    return a;
}

#define SW128(o) ((o) ^ (((o) >> 3) & 0x70))

__device__ __forceinline__ void cp16(uint32_t dst, const void* src) {
    asm volatile("cp.async.cg.shared.global [%0], [%1], 16;" :: "r"(dst), "l"(src));
}
__device__ __forceinline__ void cp_commit() {
    asm volatile("cp.async.commit_group;" ::: "memory");
}
template <int N>
__device__ __forceinline__ void cp_wait() {
    asm volatile("cp.async.wait_group %0;" :: "n"(N) : "memory");
}

__device__ __forceinline__ void ldsm4(uint32_t* r, uint32_t addr) {
    asm volatile("ldmatrix.sync.aligned.m8n8.x4.shared.b16 {%0,%1,%2,%3}, [%4];"
        : "=r"(r[0]), "=r"(r[1]), "=r"(r[2]), "=r"(r[3]) : "r"(addr));
}

__device__ __forceinline__ void mma16816(float* c, const uint32_t* a,
                                         uint32_t b0, uint32_t b1) {
    asm volatile(
        "mma.sync.aligned.m16n8k16.row.col.f32.bf16.bf16.f32 "
        "{%0,%1,%2,%3}, {%4,%5,%6,%7}, {%8,%9}, {%0,%1,%2,%3};"
        : "+f"(c[0]), "+f"(c[1]), "+f"(c[2]), "+f"(c[3])
        : "r"(a[0]), "r"(a[1]), "r"(a[2]), "r"(a[3]), "r"(b0), "r"(b1));
}

__device__ __forceinline__ void split_bf(float v, __nv_bfloat16& h, __nv_bfloat16& l) {
    h = __float2bfloat16(v);
    l = __float2bfloat16(v - __bfloat162float(h));
}
__device__ __forceinline__ uint32_t pack2(__nv_bfloat16 a, __nv_bfloat16 b) {
    __nv_bfloat162 t; t.x = a; t.y = b;
    return *reinterpret_cast<uint32_t*>(&t);
}

// ============================================================
// fp32 -> bf16 hi/lo split conversions (+ zero g_cnt piggyback)
// ============================================================
__global__ void conv_x_kernel(const float* __restrict__ x) {
    size_t i4 = (size_t)blockIdx.x * blockDim.x + threadIdx.x;
    if (i4 < NN) g_cnt[i4] = 0;          // piggyback: zero the CSR histogram
    if (i4 >= (size_t)NP * 64) return;
    float4 v = make_float4(0.f, 0.f, 0.f, 0.f);
    if (i4 < (size_t)NN * 64) v = __ldg(((const float4*)x) + i4);
    __nv_bfloat16 h0, l0, h1, l1, h2, l2, h3, l3;
    split_bf(v.x, h0, l0); split_bf(v.y, h1, l1);
    split_bf(v.z, h2, l2); split_bf(v.w, h3, l3);
    ((uint2*)g_xhi)[i4] = make_uint2(pack2(h0, h1), pack2(h2, h3));
    ((uint2*)g_xlo)[i4] = make_uint2(pack2(l0, l1), pack2(l2, l3));
}

// one kernel converts all four weight matrices
__global__ void conv_w_all_kernel(const float* __restrict__ W1,
                                  const float* __restrict__ W2,
                                  const float* __restrict__ W3,
                                  const float* __restrict__ Wd1) {
    int i = blockIdx.x * blockDim.x + threadIdx.x;   // float4 index, 49152 total
    const float* w; __nv_bfloat16 *hi, *lo; int off;
    if (i < 16384)      { w = W1;  hi = g_w1hi;  lo = g_w1lo;  off = i; }
    else if (i < 24576) { w = W2;  hi = g_w2hi;  lo = g_w2lo;  off = i - 16384; }
    else if (i < 32768) { w = W3;  hi = g_w3hi;  lo = g_w3lo;  off = i - 24576; }
    else if (i < 49152) { w = Wd1; hi = g_wd1hi; lo = g_wd1lo; off = i - 32768; }
    else return;
    float4 v = __ldg(((const float4*)w) + off);
    __nv_bfloat16 h0, l0, h1, l1, h2, l2, h3, l3;
    split_bf(v.x, h0, l0); split_bf(v.y, h1, l1);
    split_bf(v.z, h2, l2); split_bf(v.w, h3, l3);
    ((uint2*)hi)[off] = make_uint2(pack2(h0, h1), pack2(h2, h3));
    ((uint2*)lo)[off] = make_uint2(pack2(l0, l1), pack2(l2, l3));
}

// ============================================================
// edge_index dtype detection + extraction (int32 vs int64)
// ============================================================
__global__ void detect_kernel(const int* __restrict__ ei) {
    int z = 1;
    for (int i = 0; i < 64; i++)
        if (ei[2 * i + 1] != 0) { z = 0; break; }
    g_is64 = z;
}

// extraction + degree histogram fused
__global__ void extract_kernel(const int* __restrict__ ei) {
    int e = blockIdx.x * blockDim.x + threadIdx.x;
    if (e >= NE) return;
    int s, d;
    if (g_is64) {
        s = __ldg(&ei[2 * e]);
        d = __ldg(&ei[2 * ((size_t)NE + e)]);
    } else {
        s = __ldg(&ei[e]);
        d = __ldg(&ei[NE + e]);
    }
    g_src[e] = s;
    g_dst[e] = d;
    if ((unsigned)d < NN) atomicAdd(&g_cnt[d], 1);
}

__global__ void scan_kernel() {
    __shared__ int sd[1024];
    int t = threadIdx.x;
    const int PER = (NN + 1023) / 1024;   // 98
    int b = t * PER;
    int e = b + PER; if (e > NN) e = NN; if (b > NN) b = NN;
    int s = 0;
    for (int i = b; i < e; i++) s += g_cnt[i];
    sd[t] = s;
    __syncthreads();
    for (int off = 1; off < 1024; off <<= 1) {
        int v = (t >= off) ? sd[t - off] : 0;
        __syncthreads();
        sd[t] += v;
        __syncthreads();
    }
    int run = sd[t] - s;   // exclusive prefix
    for (int i = b; i < e; i++) {
        g_rowptr[i] = run;
        g_cursor[i] = run;
        run += g_cnt[i];
    }
    if (t == 1023) g_rowptr[NN] = run;
}

__global__ void fill_edges_kernel() {
    int e = blockIdx.x * blockDim.x + threadIdx.x;
    if (e >= NE) return;
    unsigned s = (unsigned)g_src[e];
    unsigned d = (unsigned)g_dst[e];
    if (s < NN && d < NN) {
        int p = atomicAdd(&g_cursor[d], 1);
        g_colidx[p] = (int)s;
    }
}

// ============================================================
// GEMM via warp-level mma.sync m16n8k16 bf16, hi/lo split (3 passes)
// CTA tile: 128 rows x 256 cols. 8 warps: 2 row-warps x 4 col-warps,
// warp tile 64x64 (c[4][8][4] = 128 accum regs). K chunked at 64,
// 2-stage cp.async pipeline.
//  MODE 0: layer-1   -> relu(+b1), l2norm, write g_xhi/g_xlo
//  MODE 1: mid layer -> cols[0:128)=relu(+b2)->g_a ; cols[128:256)=raw->g_y
//  MODE 2: final     -> h=relu(+bd1); out[row] = h . wd2 + bd2
// ============================================================
static constexpr int OF_AH = 0;                 // 16 KB (128 x 128B)
static constexpr int OF_AL = 16384;             // 16 KB
static constexpr int OF_BH = 32768;             // 32 KB (256 x 128B)
static constexpr int OF_BL = 65536;             // 32 KB
static constexpr int STG   = 98304;             // per-stage bytes (96 KB)
static constexpr int SMEM_SZ = 2 * STG;         // 192 KB
static constexpr int SSTRIDE = 260;             // staging row stride (floats)

__device__ __forceinline__ void issue_chunk(
        uint32_t sbuf, int rowbase, int kb,
        const __nv_bfloat16* BloH, const __nv_bfloat16* BloL,
        const __nv_bfloat16* BupH, const __nv_bfloat16* BupL, int tid) {
    // A: 128 rows x 8 uint4-groups per precision (Kc=64 -> 128B/row)
    for (int t = tid; t < 1024; t += 256) {
        int r = t >> 3, g = t & 7;
        uint32_t so = SW128((uint32_t)(r * 128 + g * 16));
        size_t src = (size_t)(rowbase + r) * D + kb + g * 8;
        cp16(sbuf + OF_AH + so, g_xhi + src);
        cp16(sbuf + OF_AL + so, g_xlo + src);
    }
    // B: 256 rows x 8 groups per precision
    for (int t = tid; t < 2048; t += 256) {
        int r = t >> 3, g = t & 7;
        uint32_t so = SW128((uint32_t)(r * 128 + g * 16));
        const __nv_bfloat16 *sh, *sl;
        if (r < 128) {
            sh = BloH + (size_t)r * D + kb + g * 8;
            sl = BloL + (size_t)r * D + kb + g * 8;
        } else {
            sh = BupH + (size_t)(r - 128) * D + kb + g * 8;
            sl = BupL + (size_t)(r - 128) * D + kb + g * 8;
        }
        cp16(sbuf + OF_BH + so, sh);
        cp16(sbuf + OF_BL + so, sl);
    }
}

template <int MODE>
__global__ void __launch_bounds__(256, 1)
gemm_kernel(const float* __restrict__ bias, const float* __restrict__ wd2,
            const float* __restrict__ bd2, float* __restrict__ out) {
    extern __shared__ char smem[];
    uint32_t sb = smem_u32(smem);
    int tid = threadIdx.x, wid = tid >> 5, lane = tid & 31;
    int rowbase = blockIdx.x * 128;
    int wrow = wid & 1;        // 0..1  -> rows wrow*64
    int wcol = wid >> 1;       // 0..3  -> cols wcol*64

    const __nv_bfloat16 *BloH, *BloL, *BupH, *BupL;
    if (MODE == 0)      { BloH = g_w1hi;  BloL = g_w1lo;  BupH = g_w1hi + 128 * D;  BupL = g_w1lo + 128 * D; }
    else if (MODE == 1) { BloH = g_w2hi;  BloL = g_w2lo;  BupH = g_w3hi;            BupL = g_w3lo; }
    else                { BloH = g_wd1hi; BloL = g_wd1lo; BupH = g_wd1hi + 128 * D; BupL = g_wd1lo + 128 * D; }

    float c[4][8][4];
    #pragma unroll
    for (int mt = 0; mt < 4; mt++)
        #pragma unroll
        for (int nt = 0; nt < 8; nt++)
            #pragma unroll
            for (int q = 0; q < 4; q++) c[mt][nt][q] = 0.f;

    int q8 = lane >> 3, l8 = lane & 7;

    issue_chunk(sb, rowbase, 0, BloH, BloL, BupH, BupL, tid);
    cp_commit();

    for (int ch = 0; ch < 4; ch++) {
        uint32_t buf = sb + (uint32_t)(ch & 1) * STG;
        if (ch < 3) {
            issue_chunk(sb + (uint32_t)((ch + 1) & 1) * STG, rowbase,
                        (ch + 1) * 64, BloH, BloL, BupH, BupL, tid);
            cp_commit();
            cp_wait<1>();
        } else {
            cp_wait<0>();
        }
        __syncthreads();

        #pragma unroll
        for (int ks = 0; ks < 4; ks++) {
            uint32_t ah[4][4], al[4][4];
            #pragma unroll
            for (int mt = 0; mt < 4; mt++) {
                int row = wrow * 64 + mt * 16 + (q8 & 1) * 8 + l8;
                uint32_t off = SW128((uint32_t)(row * 128 + ks * 32 + (q8 >> 1) * 16));
                ldsm4(ah[mt], buf + OF_AH + off);
                ldsm4(al[mt], buf + OF_AL + off);
            }
            uint32_t bh[4][4], bl[4][4];
            #pragma unroll
            for (int nt = 0; nt < 4; nt++) {
                int nrow = wcol * 64 + nt * 16 + ((q8 >> 1) & 1) * 8 + l8;
                uint32_t off = SW128((uint32_t)(nrow * 128 + ks * 32 + (q8 & 1) * 16));
                ldsm4(bh[nt], buf + OF_BH + off);
                ldsm4(bl[nt], buf + OF_BL + off);
            }
            #pragma unroll
            for (int mt = 0; mt < 4; mt++)
                #pragma unroll
                for (int nt = 0; nt < 4; nt++) {
                    mma16816(c[mt][nt * 2],     ah[mt], bh[nt][0], bh[nt][1]);
                    mma16816(c[mt][nt * 2],     ah[mt], bl[nt][0], bl[nt][1]);
                    mma16816(c[mt][nt * 2],     al[mt], bh[nt][0], bh[nt][1]);
                    mma16816(c[mt][nt * 2 + 1], ah[mt], bh[nt][2], bh[nt][3]);
                    mma16816(c[mt][nt * 2 + 1], ah[mt], bl[nt][2], bl[nt][3]);
                    mma16816(c[mt][nt * 2 + 1], al[mt], bh[nt][2], bh[nt][3]);
                }
        }
        __syncthreads();
    }

    // ---- stage accumulators into smem (overlays the pipeline buffers)
    float* stage = reinterpret_cast<float*>(smem);
    #pragma unroll
    for (int mt = 0; mt < 4; mt++)
        #pragma unroll
        for (int nt = 0; nt < 8; nt++) {
            int r0  = wrow * 64 + mt * 16 + (lane >> 2);
            int col = wcol * 64 + nt * 8 + 2 * (lane & 3);
            float* p = stage + r0 * SSTRIDE + col;
            p[0] = c[mt][nt][0];
            p[1] = c[mt][nt][1];
            p[8 * SSTRIDE]     = c[mt][nt][2];
            p[8 * SSTRIDE + 1] = c[mt][nt][3];
        }
    __syncthreads();

    // ---- row-wise fused epilogue: warp per row, lane owns 8 contiguous cols
    for (int r = wid; r < 128; r += 8) {
        int gr = rowbase + r;
        bool ok = gr < NN;
        const float* rowp = stage + r * SSTRIDE + lane * 8;
        int cb = lane * 8;

        if (MODE == 0) {
            float v[8];
            float ss = 0.f;
            #pragma unroll
            for (int j = 0; j < 8; j++) {
                v[j] = fmaxf(rowp[j] + __ldg(&bias[cb + j]), 0.f);
                ss += v[j] * v[j];
            }
            #pragma unroll
            for (int off = 16; off >= 1; off >>= 1)
                ss += __shfl_xor_sync(0xffffffffu, ss, off);
            float rn = rsqrtf(ss);
            if (ok) {
                __nv_bfloat16 h[8], l[8];
                #pragma unroll
                for (int j = 0; j < 8; j++) split_bf(v[j] * rn, h[j], l[j]);
                *reinterpret_cast<uint4*>(g_xhi + (size_t)gr * D + cb) =
                    make_uint4(pack2(h[0], h[1]), pack2(h[2], h[3]),
                               pack2(h[4], h[5]), pack2(h[6], h[7]));
                *reinterpret_cast<uint4*>(g_xlo + (size_t)gr * D + cb) =
                    make_uint4(pack2(l[0], l[1]), pack2(l[2], l[3]),
                               pack2(l[4], l[5]), pack2(l[6], l[7]));
            }
        } else if (MODE == 1) {
            float v[8];
            if (lane < 16) {
                #pragma unroll
                for (int j = 0; j < 8; j++)
                    v[j] = fmaxf(rowp[j] + __ldg(&bias[cb + j]), 0.f);
                if (ok) {
                    float4* dst = reinterpret_cast<float4*>(g_a + (size_t)gr * DH + cb);
                    dst[0] = make_float4(v[0], v[1], v[2], v[3]);
                    dst[1] = make_float4(v[4], v[5], v[6], v[7]);
                }
            } else {
                #pragma unroll
                for (int j = 0; j < 8; j++) v[j] = rowp[j];
                if (ok) {
                    float4* dst = reinterpret_cast<float4*>(g_y + (size_t)gr * DH + (cb - 128));
                    dst[0] = make_float4(v[0], v[1], v[2], v[3]);
                    dst[1] = make_float4(v[4], v[5], v[6], v[7]);
                }
            }
        } else {
            float acc = 0.f;
            #pragma unroll
            for (int j = 0; j < 8; j++) {
                float vv = fmaxf(rowp[j] + __ldg(&bias[cb + j]), 0.f);
                acc += vv * __ldg(&wd2[cb + j]);
            }
            #pragma unroll
            for (int off = 16; off >= 1; off >>= 1)
                acc += __shfl_xor_sync(0xffffffffu, acc, off);
            if (lane == 0 && ok) out[gr] = acc + __ldg(bd2);
        }
    }
}

// ============================================================
// Fused CSR gather-reduce + bias + relu + l2norm + bf16-split store
// One warp per dst node; lane owns 4 cols of each 128-wide half.
// Gather loop unrolled x4 for MLP.
// ============================================================
__global__ void agg_combine_kernel(const float* __restrict__ b3) {
    int gw = (blockIdx.x * blockDim.x + threadIdx.x) >> 5;
    int lane = threadIdx.x & 31;
    if (gw >= NN) return;
    int n = gw;
    int beg = __ldg(&g_rowptr[n]);
    int end = __ldg(&g_rowptr[n + 1]);

    float ax = 0.f, ay = 0.f, az = 0.f, aw = 0.f;
    int i = beg;
    for (; i + 4 <= end; i += 4) {
        int s0 = __ldg(&g_colidx[i]);
        int s1 = __ldg(&g_colidx[i + 1]);
        int s2 = __ldg(&g_colidx[i + 2]);
        int s3 = __ldg(&g_colidx[i + 3]);
        float4 v0 = __ldg(reinterpret_cast<const float4*>(g_y + (size_t)s0 * DH) + lane);
        float4 v1 = __ldg(reinterpret_cast<const float4*>(g_y + (size_t)s1 * DH) + lane);
        float4 v2 = __ldg(reinterpret_cast<const float4*>(g_y + (size_t)s2 * DH) + lane);
        float4 v3 = __ldg(reinterpret_cast<const float4*>(g_y + (size_t)s3 * DH) + lane);
        ax += v0.x + v1.x + v2.x + v3.x;
        ay += v0.y + v1.y + v2.y + v3.y;
        az += v0.z + v1.z + v2.z + v3.z;
        aw += v0.w + v1.w + v2.w + v3.w;
    }
    for (; i < end; i++) {
        int s = __ldg(&g_colidx[i]);
        float4 v = __ldg(reinterpret_cast<const float4*>(g_y + (size_t)s * DH) + lane);
        ax += v.x; ay += v.y; az += v.z; aw += v.w;
    }

    float4 av = *(reinterpret_cast<const float4*>(g_a + (size_t)n * DH) + lane);
    float4 bb = __ldg(reinterpret_cast<const float4*>(b3) + lane);
    float m0 = fmaxf(ax + bb.x, 0.f);
    float m1 = fmaxf(ay + bb.y, 0.f);
    float m2 = fmaxf(az + bb.z, 0.f);
    float m3 = fmaxf(aw + bb.w, 0.f);

    float ss = av.x * av.x + av.y * av.y + av.z * av.z + av.w * av.w
             + m0 * m0 + m1 * m1 + m2 * m2 + m3 * m3;
    #pragma unroll
    for (int off = 16; off >= 1; off >>= 1)
        ss += __shfl_xor_sync(0xffffffffu, ss, off);
    float rn = rsqrtf(ss);

    size_t base = (size_t)n * D;
    {
        __nv_bfloat16 h0, l0, h1, l1, h2, l2, h3, l3;
        split_bf(av.x * rn, h0, l0); split_bf(av.y * rn, h1, l1);
        split_bf(av.z * rn, h2, l2); split_bf(av.w * rn, h3, l3);
        *reinterpret_cast<uint2*>(g_xhi + base + lane * 4) = make_uint2(pack2(h0, h1), pack2(h2, h3));
        *reinterpret_cast<uint2*>(g_xlo + base + lane * 4) = make_uint2(pack2(l0, l1), pack2(l2, l3));
    }
    {
        __nv_bfloat16 h0, l0, h1, l1, h2, l2, h3, l3;
        split_bf(m0 * rn, h0, l0); split_bf(m1 * rn, h1, l1);
        split_bf(m2 * rn, h2, l2); split_bf(m3 * rn, h3, l3);
        *reinterpret_cast<uint2*>(g_xhi + base + 128 + lane * 4) = make_uint2(pack2(h0, h1), pack2(h2, h3));
        *reinterpret_cast<uint2*>(g_xlo + base + 128 + lane * 4) = make_uint2(pack2(l0, l1), pack2(l2, l3));
    }
}

// ============================================================
// Host launcher
// ============================================================
extern "C" void kernel_launch(void* const* d_in, const int* in_sizes, int n_in,
                              void* d_out, int out_size) {
    const float* x   = (const float*)d_in[0];
    const int*   ei  = (const int*)d_in[1];    // int32 or int64 (auto-detected)
    const float* W1  = (const float*)d_in[2];
    const float* b1  = (const float*)d_in[3];
    const float* W2  = (const float*)d_in[4];
    const float* b2  = (const float*)d_in[5];
    const float* W3  = (const float*)d_in[6];
    const float* b3  = (const float*)d_in[7];
    const float* Wd1 = (const float*)d_in[8];
    const float* bd1 = (const float*)d_in[9];
    const float* Wd2 = (const float*)d_in[10];
    const float* bd2 = (const float*)d_in[11];
    float* out = (float*)d_out;

    cudaFuncSetAttribute(gemm_kernel<0>, cudaFuncAttributeMaxDynamicSharedMemorySize, SMEM_SZ);
    cudaFuncSetAttribute(gemm_kernel<1>, cudaFuncAttributeMaxDynamicSharedMemorySize, SMEM_SZ);
    cudaFuncSetAttribute(gemm_kernel<2>, cudaFuncAttributeMaxDynamicSharedMemorySize, SMEM_SZ);

    // input conversions (fp32 -> bf16 hi/lo); conv_x also zeroes g_cnt
    conv_x_kernel<<<(int)(((size_t)NP * 64 + 255) / 256), 256>>>(x);
    conv_w_all_kernel<<<192, 256>>>(W1, W2, W3, Wd1);

    // edge extraction (+degree count) + CSR build (by dst)
    detect_kernel<<<1, 1>>>(ei);
    extract_kernel<<<(NE + 255) / 256, 256>>>(ei);
    scan_kernel<<<1, 1024>>>();
    fill_edges_kernel<<<(NE + 255) / 256, 256>>>();

    // layer 1: x = l2norm(relu(x @ W1^T + b1))
    gemm_kernel<0><<<NB128, 256, SMEM_SZ>>>(b1, nullptr, nullptr, nullptr);

    // 2 conv layers
    for (int l = 0; l < 2; l++) {
        gemm_kernel<1><<<NB128, 256, SMEM_SZ>>>(b2, nullptr, nullptr, nullptr);
        agg_combine_kernel<<<(NN * 32 + 255) / 256, 256>>>(b3);
    }

    // head: out = relu(x @ Wd1^T + bd1) @ Wd2^T + bd2
    gemm_kernel<2><<<NB128, 256, SMEM_SZ>>>(bd1, Wd2, bd2, out);
}

// round 6
// speedup vs baseline: 1.1748x; 1.1421x over previous
#include <cuda_runtime.h>
#include <cuda_bf16.h>
#include <cuda_fp16.h>
#include <cstdint>
#include <cstddef>

// ============================================================
// Problem constants
// ============================================================
#define NN   100000      // nodes
#define NE   1600000     // edges
#define NP   100096      // padded: 128*782
#define NB128 782        // GEMM row tiles (128 rows each)
#define D    256
#define DH   128

// ============================================================
// Device global scratch (no cudaMalloc allowed)
// ============================================================
__device__ __align__(256) __nv_bfloat16 g_xhi[(size_t)NP * D];   // layer-1 input hi
__device__ __align__(256) __nv_bfloat16 g_xlo[(size_t)NP * D];   // layer-1 input lo
__device__ __align__(256) __half g_h[(size_t)NP * D];            // activations (fp16 single)
__device__ __align__(256) float g_a[(size_t)NP * DH];   // relu(x@W2^T + b2)
__device__ __align__(256) float g_y[(size_t)NP * DH];   // x@W3^T (pre-aggregation)
__device__ __align__(256) __nv_bfloat16 g_w1hi[D * D],  g_w1lo[D * D];
__device__ __align__(256) __half g_w2hi[DH * D], g_w2lo[DH * D];
__device__ __align__(256) __half g_w3hi[DH * D], g_w3lo[DH * D];
__device__ __align__(256) __half g_wd1hi[D * D], g_wd1lo[D * D];
__device__ __align__(256) int g_rowptr[NN + 1];
__device__ __align__(256) int g_cursor[NN];
__device__ __align__(256) int g_cnt[NN];
__device__ __align__(256) int g_colidx[NE];
__device__ __align__(256) int g_src[NE];
__device__ __align__(256) int g_dst[NE];
__device__ int g_is64;

// ============================================================
// Helpers
// ============================================================
__device__ __forceinline__ uint32_t smem_u32(const void* p) {
    uint32_t a;
    asm("{ .reg .u64 t; cvta.to.shared.u64 t, %1; cvt.u32.u64 %0, t; }"
        : "=r"(a) : "l"(p));
    return a;
}

#define SW128(o) ((o) ^ (((o) >> 3) & 0x70))

__device__ __forceinline__ void cp16(uint32_t dst, const void* src) {
    asm volatile("cp.async.cg.shared.global [%0], [%1], 16;" :: "r"(dst), "l"(src));
}
__device__ __forceinline__ void cp_commit() {
    asm volatile("cp.async.commit_group;" ::: "memory");
}
template <int N>
__device__ __forceinline__ void cp_wait() {
    asm volatile("cp.async.wait_group %0;" :: "n"(N) : "memory");
}

__device__ __forceinline__ void ldsm4(uint32_t* r, uint32_t addr) {
    asm volatile("ldmatrix.sync.aligned.m8n8.x4.shared.b16 {%0,%1,%2,%3}, [%4];"
        : "=r"(r[0]), "=r"(r[1]), "=r"(r[2]), "=r"(r[3]) : "r"(addr));
}

__device__ __forceinline__ void mma_bf16(float* c, const uint32_t* a,
                                         uint32_t b0, uint32_t b1) {
    asm volatile(
        "mma.sync.aligned.m16n8k16.row.col.f32.bf16.bf16.f32 "
        "{%0,%1,%2,%3}, {%4,%5,%6,%7}, {%8,%9}, {%0,%1,%2,%3};"
        : "+f"(c[0]), "+f"(c[1]), "+f"(c[2]), "+f"(c[3])
        : "r"(a[0]), "r"(a[1]), "r"(a[2]), "r"(a[3]), "r"(b0), "r"(b1));
}
__device__ __forceinline__ void mma_f16(float* c, const uint32_t* a,
                                        uint32_t b0, uint32_t b1) {
    asm volatile(
        "mma.sync.aligned.m16n8k16.row.col.f32.f16.f16.f32 "
        "{%0,%1,%2,%3}, {%4,%5,%6,%7}, {%8,%9}, {%0,%1,%2,%3};"
        : "+f"(c[0]), "+f"(c[1]), "+f"(c[2]), "+f"(c[3])
        : "r"(a[0]), "r"(a[1]), "r"(a[2]), "r"(a[3]), "r"(b0), "r"(b1));
}

__device__ __forceinline__ void split_bf(float v, __nv_bfloat16& h, __nv_bfloat16& l) {
    h = __float2bfloat16(v);
    l = __float2bfloat16(v - __bfloat162float(h));
}
__device__ __forceinline__ void split_hf(float v, __half& h, __half& l) {
    h = __float2half_rn(v);
    l = __float2half_rn(v - __half2float(h));
}
__device__ __forceinline__ uint32_t pack2(__nv_bfloat16 a, __nv_bfloat16 b) {
    __nv_bfloat162 t; t.x = a; t.y = b;
    return *reinterpret_cast<uint32_t*>(&t);
}
__device__ __forceinline__ uint32_t pack2h(__half a, __half b) {
    __half2 t; t.x = a; t.y = b;
    return *reinterpret_cast<uint32_t*>(&t);
}

// ============================================================
// fp32 -> bf16 hi/lo split of x (+ zero g_cnt piggyback)
// ============================================================
__global__ void conv_x_kernel(const float* __restrict__ x) {
    size_t i4 = (size_t)blockIdx.x * blockDim.x + threadIdx.x;
    if (i4 < NN) g_cnt[i4] = 0;          // piggyback: zero the CSR histogram
    if (i4 >= (size_t)NP * 64) return;
    float4 v = make_float4(0.f, 0.f, 0.f, 0.f);
    if (i4 < (size_t)NN * 64) v = __ldg(((const float4*)x) + i4);
    __nv_bfloat16 h0, l0, h1, l1, h2, l2, h3, l3;
    split_bf(v.x, h0, l0); split_bf(v.y, h1, l1);
    split_bf(v.z, h2, l2); split_bf(v.w, h3, l3);
    ((uint2*)g_xhi)[i4] = make_uint2(pack2(h0, h1), pack2(h2, h3));
    ((uint2*)g_xlo)[i4] = make_uint2(pack2(l0, l1), pack2(l2, l3));
}

// one kernel converts all four weight matrices
// W1 -> bf16 hi/lo, W2/W3/Wd1 -> fp16 hi/lo
__global__ void conv_w_all_kernel(const float* __restrict__ W1,
                                  const float* __restrict__ W2,
                                  const float* __restrict__ W3,
                                  const float* __restrict__ Wd1) {
    int i = blockIdx.x * blockDim.x + threadIdx.x;   // float4 index, 49152 total
    if (i < 16384) {
        float4 v = __ldg(((const float4*)W1) + i);
        __nv_bfloat16 h0, l0, h1, l1, h2, l2, h3, l3;
        split_bf(v.x, h0, l0); split_bf(v.y, h1, l1);
        split_bf(v.z, h2, l2); split_bf(v.w, h3, l3);
        ((uint2*)g_w1hi)[i] = make_uint2(pack2(h0, h1), pack2(h2, h3));
        ((uint2*)g_w1lo)[i] = make_uint2(pack2(l0, l1), pack2(l2, l3));
        return;
    }
    const float* w; __half *hi, *lo; int off;
    if (i < 24576)      { w = W2;  hi = g_w2hi;  lo = g_w2lo;  off = i - 16384; }
    else if (i < 32768) { w = W3;  hi = g_w3hi;  lo = g_w3lo;  off = i - 24576; }
    else if (i < 49152) { w = Wd1; hi = g_wd1hi; lo = g_wd1lo; off = i - 32768; }
    else return;
    float4 v = __ldg(((const float4*)w) + off);
    __half h0, l0, h1, l1, h2, l2, h3, l3;
    split_hf(v.x, h0, l0); split_hf(v.y, h1, l1);
    split_hf(v.z, h2, l2); split_hf(v.w, h3, l3);
    ((uint2*)hi)[off] = make_uint2(pack2h(h0, h1), pack2h(h2, h3));
    ((uint2*)lo)[off] = make_uint2(pack2h(l0, l1), pack2h(l2, l3));
}

// ============================================================
// edge_index dtype detection + extraction (int32 vs int64)
// ============================================================
__global__ void detect_kernel(const int* __restrict__ ei) {
    int z = 1;
    for (int i = 0; i < 64; i++)
        if (ei[2 * i + 1] != 0) { z = 0; break; }
    g_is64 = z;
}

__global__ void extract_kernel(const int* __restrict__ ei) {
    int e = blockIdx.x * blockDim.x + threadIdx.x;
    if (e >= NE) return;
    int s, d;
    if (g_is64) {
        s = __ldg(&ei[2 * e]);
        d = __ldg(&ei[2 * ((size_t)NE + e)]);
    } else {
        s = __ldg(&ei[e]);
        d = __ldg(&ei[NE + e]);
    }
    g_src[e] = s;
    g_dst[e] = d;
    if ((unsigned)d < NN) atomicAdd(&g_cnt[d], 1);
}

__global__ void scan_kernel() {
    __shared__ int sd[1024];
    int t = threadIdx.x;
    const int PER = (NN + 1023) / 1024;   // 98
    int b = t * PER;
    int e = b + PER; if (e > NN) e = NN; if (b > NN) b = NN;
    int s = 0;
    for (int i = b; i < e; i++) s += g_cnt[i];
    sd[t] = s;
    __syncthreads();
    for (int off = 1; off < 1024; off <<= 1) {
        int v = (t >= off) ? sd[t - off] : 0;
        __syncthreads();
        sd[t] += v;
        __syncthreads();
    }
    int run = sd[t] - s;   // exclusive prefix
    for (int i = b; i < e; i++) {
        g_rowptr[i] = run;
        g_cursor[i] = run;
        run += g_cnt[i];
    }
    if (t == 1023) g_rowptr[NN] = run;
}

__global__ void fill_edges_kernel() {
    int e = blockIdx.x * blockDim.x + threadIdx.x;
    if (e >= NE) return;
    unsigned s = (unsigned)g_src[e];
    unsigned d = (unsigned)g_dst[e];
    if (s < NN && d < NN) {
        int p = atomicAdd(&g_cursor[d], 1);
        g_colidx[p] = (int)s;
    }
}

// ============================================================
// GEMM: CTA tile 128x256, 8 warps (2 row x 4 col), warp tile 64x64,
// K chunked at 64, 2-stage cp.async pipeline.
//  MODE 0: layer-1, bf16 3-pass exact (A=g_xhi/g_xlo, B=W1 hi/lo)
//           -> relu(+b1), l2norm, write g_h (fp16)
//  MODE 1: mid, fp16 2-pass (A=g_h single, B=[W2;W3] hi/lo)
//           -> cols[0:128)=relu(+b2)->g_a ; cols[128:256)=raw->g_y
//  MODE 2: final, fp16 2-pass (A=g_h, B=Wd1 hi/lo)
//           -> h=relu(+bd1); out[row] = h . wd2 + bd2
// ============================================================
static constexpr int SSTRIDE = 260;             // staging row stride (floats)

template <int MODE>
struct GCfg {
    static constexpr bool BF   = (MODE == 0);
    static constexpr int OF_AL = 16384;                 // only used when BF
    static constexpr int OF_BH = BF ? 32768 : 16384;
    static constexpr int OF_BL = BF ? 65536 : 49152;
    static constexpr int STG   = BF ? 98304 : 81920;
    static constexpr int SMEM  = 2 * STG;
};

template <int MODE>
__device__ __forceinline__ void issue_chunk(
        uint32_t sbuf, int rowbase, int kb, int tid,
        const uint8_t* BloH, const uint8_t* BloL,
        const uint8_t* BupH, const uint8_t* BupL) {
    using C = GCfg<MODE>;
    // A: 128 rows x 8 groups of 16B (Kc=64 x 2B = 128B/row)
    for (int t = tid; t < 1024; t += 256) {
        int r = t >> 3, g = t & 7;
        uint32_t so = SW128((uint32_t)(r * 128 + g * 16));
        size_t ob = ((size_t)(rowbase + r) * D + kb + g * 8) * 2;
        if (C::BF) {
            cp16(sbuf + so,            (const uint8_t*)g_xhi + ob);
            cp16(sbuf + C::OF_AL + so, (const uint8_t*)g_xlo + ob);
        } else {
            cp16(sbuf + so,            (const uint8_t*)g_h + ob);
        }
    }
    // B: 256 rows x 8 groups (hi + lo)
    for (int t = tid; t < 2048; t += 256) {
        int r = t >> 3, g = t & 7;
        uint32_t so = SW128((uint32_t)(r * 128 + g * 16));
        size_t ob = ((size_t)(r < 128 ? r : r - 128) * D + kb + g * 8) * 2;
        const uint8_t* sh = (r < 128 ? BloH : BupH) + ob;
        const uint8_t* sl = (r < 128 ? BloL : BupL) + ob;
        cp16(sbuf + C::OF_BH + so, sh);
        cp16(sbuf + C::OF_BL + so, sl);
    }
}

template <int MODE>
__global__ void __launch_bounds__(256, 1)
gemm_kernel(const float* __restrict__ bias, const float* __restrict__ wd2,
            const float* __restrict__ bd2, float* __restrict__ out) {
    using C = GCfg<MODE>;
    extern __shared__ char smem[];
    uint32_t sb = smem_u32(smem);
    int tid = threadIdx.x, wid = tid >> 5, lane = tid & 31;
    int rowbase = blockIdx.x * 128;
    int wrow = wid & 1;        // 0..1  -> rows wrow*64
    int wcol = wid >> 1;       // 0..3  -> cols wcol*64

    const uint8_t *BloH, *BloL, *BupH, *BupL;
    if (MODE == 0) {
        BloH = (const uint8_t*)g_w1hi;  BloL = (const uint8_t*)g_w1lo;
        BupH = (const uint8_t*)(g_w1hi + 128 * D);  BupL = (const uint8_t*)(g_w1lo + 128 * D);
    } else if (MODE == 1) {
        BloH = (const uint8_t*)g_w2hi;  BloL = (const uint8_t*)g_w2lo;
        BupH = (const uint8_t*)g_w3hi;  BupL = (const uint8_t*)g_w3lo;
    } else {
        BloH = (const uint8_t*)g_wd1hi; BloL = (const uint8_t*)g_wd1lo;
        BupH = (const uint8_t*)(g_wd1hi + 128 * D); BupL = (const uint8_t*)(g_wd1lo + 128 * D);
    }

    float c[4][8][4];
    #pragma unroll
    for (int mt = 0; mt < 4; mt++)
        #pragma unroll
        for (int nt = 0; nt < 8; nt++)
            #pragma unroll
            for (int q = 0; q < 4; q++) c[mt][nt][q] = 0.f;

    int q8 = lane >> 3, l8 = lane & 7;

    issue_chunk<MODE>(sb, rowbase, 0, tid, BloH, BloL, BupH, BupL);
    cp_commit();

    for (int ch = 0; ch < 4; ch++) {
        uint32_t buf = sb + (uint32_t)(ch & 1) * C::STG;
        if (ch < 3) {
            issue_chunk<MODE>(sb + (uint32_t)((ch + 1) & 1) * C::STG, rowbase,
                              (ch + 1) * 64, tid, BloH, BloL, BupH, BupL);
            cp_commit();
            cp_wait<1>();
        } else {
            cp_wait<0>();
        }
        __syncthreads();

        #pragma unroll
        for (int ks = 0; ks < 4; ks++) {
            uint32_t ah[4][4], al[4][4];
            #pragma unroll
            for (int mt = 0; mt < 4; mt++) {
                int row = wrow * 64 + mt * 16 + (q8 & 1) * 8 + l8;
                uint32_t off = SW128((uint32_t)(row * 128 + ks * 32 + (q8 >> 1) * 16));
                ldsm4(ah[mt], buf + off);
                if (C::BF) ldsm4(al[mt], buf + C::OF_AL + off);
            }
            uint32_t bh[4][4], bl[4][4];
            #pragma unroll
            for (int nt = 0; nt < 4; nt++) {
                int nrow = wcol * 64 + nt * 16 + ((q8 >> 1) & 1) * 8 + l8;
                uint32_t off = SW128((uint32_t)(nrow * 128 + ks * 32 + (q8 & 1) * 16));
                ldsm4(bh[nt], buf + C::OF_BH + off);
                ldsm4(bl[nt], buf + C::OF_BL + off);
            }
            #pragma unroll
            for (int mt = 0; mt < 4; mt++)
                #pragma unroll
                for (int nt = 0; nt < 4; nt++) {
                    if (C::BF) {
                        mma_bf16(c[mt][nt * 2],     ah[mt], bh[nt][0], bh[nt][1]);
                        mma_bf16(c[mt][nt * 2],     ah[mt], bl[nt][0], bl[nt][1]);
                        mma_bf16(c[mt][nt * 2],     al[mt], bh[nt][0], bh[nt][1]);
                        mma_bf16(c[mt][nt * 2 + 1], ah[mt], bh[nt][2], bh[nt][3]);
                        mma_bf16(c[mt][nt * 2 + 1], ah[mt], bl[nt][2], bl[nt][3]);
                        mma_bf16(c[mt][nt * 2 + 1], al[mt], bh[nt][2], bh[nt][3]);
                    } else {
                        mma_f16(c[mt][nt * 2],     ah[mt], bh[nt][0], bh[nt][1]);
                        mma_f16(c[mt][nt * 2],     ah[mt], bl[nt][0], bl[nt][1]);
                        mma_f16(c[mt][nt * 2 + 1], ah[mt], bh[nt][2], bh[nt][3]);
                        mma_f16(c[mt][nt * 2 + 1], ah[mt], bl[nt][2], bl[nt][3]);
                    }
                }
        }
        __syncthreads();
    }

    // ---- stage accumulators into smem (overlays the pipeline buffers)
    float* stage = reinterpret_cast<float*>(smem);
    #pragma unroll
    for (int mt = 0; mt < 4; mt++)
        #pragma unroll
        for (int nt = 0; nt < 8; nt++) {
            int r0  = wrow * 64 + mt * 16 + (lane >> 2);
            int col = wcol * 64 + nt * 8 + 2 * (lane & 3);
            float* p = stage + r0 * SSTRIDE + col;
            p[0] = c[mt][nt][0];
            p[1] = c[mt][nt][1];
            p[8 * SSTRIDE]     = c[mt][nt][2];
            p[8 * SSTRIDE + 1] = c[mt][nt][3];
        }
    __syncthreads();

    // ---- row-wise fused epilogue: warp per row, lane owns 8 contiguous cols
    for (int r = wid; r < 128; r += 8) {
        int gr = rowbase + r;
        bool ok = gr < NN;
        const float* rowp = stage + r * SSTRIDE + lane * 8;
        int cb = lane * 8;

        if (MODE == 0) {
            float v[8];
            float ss = 0.f;
            #pragma unroll
            for (int j = 0; j < 8; j++) {
                v[j] = fmaxf(rowp[j] + __ldg(&bias[cb + j]), 0.f);
                ss += v[j] * v[j];
            }
            #pragma unroll
            for (int off = 16; off >= 1; off >>= 1)
                ss += __shfl_xor_sync(0xffffffffu, ss, off);
            float rn = rsqrtf(ss);
            if (ok) {
                __half h[8];
                #pragma unroll
                for (int j = 0; j < 8; j++) h[j] = __float2half_rn(v[j] * rn);
                *reinterpret_cast<uint4*>(g_h + (size_t)gr * D + cb) =
                    make_uint4(pack2h(h[0], h[1]), pack2h(h[2], h[3]),
                               pack2h(h[4], h[5]), pack2h(h[6], h[7]));
            }
        } else if (MODE == 1) {
            float v[8];
            if (lane < 16) {
                #pragma unroll
                for (int j = 0; j < 8; j++)
                    v[j] = fmaxf(rowp[j] + __ldg(&bias[cb + j]), 0.f);
                if (ok) {
                    float4* dst = reinterpret_cast<float4*>(g_a + (size_t)gr * DH + cb);
                    dst[0] = make_float4(v[0], v[1], v[2], v[3]);
                    dst[1] = make_float4(v[4], v[5], v[6], v[7]);
                }
            } else {
                #pragma unroll
                for (int j = 0; j < 8; j++) v[j] = rowp[j];
                if (ok) {
                    float4* dst = reinterpret_cast<float4*>(g_y + (size_t)gr * DH + (cb - 128));
                    dst[0] = make_float4(v[0], v[1], v[2], v[3]);
                    dst[1] = make_float4(v[4], v[5], v[6], v[7]);
                }
            }
        } else {
            float acc = 0.f;
            #pragma unroll
            for (int j = 0; j < 8; j++) {
                float vv = fmaxf(rowp[j] + __ldg(&bias[cb + j]), 0.f);
                acc += vv * __ldg(&wd2[cb + j]);
            }
            #pragma unroll
            for (int off = 16; off >= 1; off >>= 1)
                acc += __shfl_xor_sync(0xffffffffu, acc, off);
            if (lane == 0 && ok) out[gr] = acc + __ldg(bd2);
        }
    }
}

// ============================================================
// Fused CSR gather-reduce + bias + relu + l2norm + fp16 store
// One warp per dst node; lane owns 4 cols of each 128-wide half.
// Gather loop unrolled x4 for MLP.
// ============================================================
__global__ void agg_combine_kernel(const float* __restrict__ b3) {
    int gw = (blockIdx.x * blockDim.x + threadIdx.x) >> 5;
    int lane = threadIdx.x & 31;
    if (gw >= NN) return;
    int n = gw;
    int beg = __ldg(&g_rowptr[n]);
    int end = __ldg(&g_rowptr[n + 1]);

    float ax = 0.f, ay = 0.f, az = 0.f, aw = 0.f;
    int i = beg;
    for (; i + 4 <= end; i += 4) {
        int s0 = __ldg(&g_colidx[i]);
        int s1 = __ldg(&g_colidx[i + 1]);
        int s2 = __ldg(&g_colidx[i + 2]);
        int s3 = __ldg(&g_colidx[i + 3]);
        float4 v0 = __ldg(reinterpret_cast<const float4*>(g_y + (size_t)s0 * DH) + lane);
        float4 v1 = __ldg(reinterpret_cast<const float4*>(g_y + (size_t)s1 * DH) + lane);
        float4 v2 = __ldg(reinterpret_cast<const float4*>(g_y + (size_t)s2 * DH) + lane);
        float4 v3 = __ldg(reinterpret_cast<const float4*>(g_y + (size_t)s3 * DH) + lane);
        ax += v0.x + v1.x + v2.x + v3.x;
        ay += v0.y + v1.y + v2.y + v3.y;
        az += v0.z + v1.z + v2.z + v3.z;
        aw += v0.w + v1.w + v2.w + v3.w;
    }
    for (; i < end; i++) {
        int s = __ldg(&g_colidx[i]);
        float4 v = __ldg(reinterpret_cast<const float4*>(g_y + (size_t)s * DH) + lane);
        ax += v.x; ay += v.y; az += v.z; aw += v.w;
    }

    float4 av = *(reinterpret_cast<const float4*>(g_a + (size_t)n * DH) + lane);
    float4 bb = __ldg(reinterpret_cast<const float4*>(b3) + lane);
    float m0 = fmaxf(ax + bb.x, 0.f);
    float m1 = fmaxf(ay + bb.y, 0.f);
    float m2 = fmaxf(az + bb.z, 0.f);
    float m3 = fmaxf(aw + bb.w, 0.f);

    float ss = av.x * av.x + av.y * av.y + av.z * av.z + av.w * av.w
             + m0 * m0 + m1 * m1 + m2 * m2 + m3 * m3;
    #pragma unroll
    for (int off = 16; off >= 1; off >>= 1)
        ss += __shfl_xor_sync(0xffffffffu, ss, off);
    float rn = rsqrtf(ss);

    size_t base = (size_t)n * D;
    *reinterpret_cast<uint2*>(g_h + base + lane * 4) =
        make_uint2(pack2h(__float2half_rn(av.x * rn), __float2half_rn(av.y * rn)),
                   pack2h(__float2half_rn(av.z * rn), __float2half_rn(av.w * rn)));
    *reinterpret_cast<uint2*>(g_h + base + 128 + lane * 4) =
        make_uint2(pack2h(__float2half_rn(m0 * rn), __float2half_rn(m1 * rn)),
                   pack2h(__float2half_rn(m2 * rn), __float2half_rn(m3 * rn)));
}

// ============================================================
// Host launcher
// ============================================================
extern "C" void kernel_launch(void* const* d_in, const int* in_sizes, int n_in,
                              void* d_out, int out_size) {
    const float* x   = (const float*)d_in[0];
    const int*   ei  = (const int*)d_in[1];    // int32 or int64 (auto-detected)
    const float* W1  = (const float*)d_in[2];
    const float* b1  = (const float*)d_in[3];
    const float* W2  = (const float*)d_in[4];
    const float* b2  = (const float*)d_in[5];
    const float* W3  = (const float*)d_in[6];
    const float* b3  = (const float*)d_in[7];
    const float* Wd1 = (const float*)d_in[8];
    const float* bd1 = (const float*)d_in[9];
    const float* Wd2 = (const float*)d_in[10];
    const float* bd2 = (const float*)d_in[11];
    float* out = (float*)d_out;

    cudaFuncSetAttribute(gemm_kernel<0>, cudaFuncAttributeMaxDynamicSharedMemorySize, GCfg<0>::SMEM);
    cudaFuncSetAttribute(gemm_kernel<1>, cudaFuncAttributeMaxDynamicSharedMemorySize, GCfg<1>::SMEM);
    cudaFuncSetAttribute(gemm_kernel<2>, cudaFuncAttributeMaxDynamicSharedMemorySize, GCfg<2>::SMEM);

    // input conversions; conv_x also zeroes g_cnt
    conv_x_kernel<<<(int)(((size_t)NP * 64 + 255) / 256), 256>>>(x);
    conv_w_all_kernel<<<192, 256>>>(W1, W2, W3, Wd1);

    // edge extraction (+degree count) + CSR build (by dst)
    detect_kernel<<<1, 1>>>(ei);
    extract_kernel<<<(NE + 255) / 256, 256>>>(ei);
    scan_kernel<<<1, 1024>>>();
    fill_edges_kernel<<<(NE + 255) / 256, 256>>>();

    // layer 1: h = fp16(l2norm(relu(x @ W1^T + b1)))   [bf16 3-pass exact]
    gemm_kernel<0><<<NB128, 256, GCfg<0>::SMEM>>>(b1, nullptr, nullptr, nullptr);

    // 2 conv layers  [fp16 2-pass]
    for (int l = 0; l < 2; l++) {
        gemm_kernel<1><<<NB128, 256, GCfg<1>::SMEM>>>(b2, nullptr, nullptr, nullptr);
        agg_combine_kernel<<<(NN * 32 + 255) / 256, 256>>>(b3);
    }

    // head: out = relu(h @ Wd1^T + bd1) @ Wd2^T + bd2   [fp16 2-pass]
    gemm_kernel<2><<<NB128, 256, GCfg<2>::SMEM>>>(bd1, Wd2, bd2, out);
}